// round 4
// baseline (speedup 1.0000x reference)
#include <cuda_runtime.h>

// ---------------------------------------------------------------------------
// Temporal attention, B=2, H=W=64, C=128, GROUPS=8 (cg=16), K=7, PAD=3, REFINE
// Stage 1: conv1x1 GEMMs -> g_Q, g_K, g_V   (layout [ch][b*4096 + h*64 + w])
// Stage 2: fused windowed attention, 16x32 tile / 512 threads.
//          No running-max in softmax: logits are O(+-55), exp() cannot
//          overflow fp32, ratios are exact -> positions fully independent.
// ---------------------------------------------------------------------------

#define HH   64
#define WW   64
#define BB   2
#define NCH  128
#define NPOS 8192            // BB*HH*WW

__device__ float g_Q[NCH * NPOS];
__device__ float g_K[NCH * NPOS];
__device__ float g_V[NCH * NPOS];

// ---------------------------------------------------------------------------
// Stage 1: C[o][p] = sum_c W[o][c] * X[c][p]   (z: 0=K,1=V,2=Q)
// ---------------------------------------------------------------------------
__global__ void __launch_bounds__(256) conv_gemm_kernel(
    const float* __restrict__ fm,
    const float* __restrict__ wq,
    const float* __restrict__ wk,
    const float* __restrict__ wv)
{
    const int z = blockIdx.z;
    const float* Wm = (z == 0) ? wk : (z == 1) ? wv : wq;
    float* C        = (z == 0) ? g_K : (z == 1) ? g_V : g_Q;
    const int cbase = (z == 2) ? 128 : 0;

    const int p0 = blockIdx.x * 64;
    const int o0 = blockIdx.y * 64;
    const int b   = p0 >> 12;
    const int hw0 = p0 & 4095;
    const float* Xbase = fm + (size_t)b * (256 * 4096) + (size_t)cbase * 4096 + hw0;

    __shared__ float As[16][68];
    __shared__ float Bs[16][64];

    const int tid  = threadIdx.x;
    const int tx   = tid & 15;
    const int ty   = tid >> 4;
    const int a_row = tid >> 2, a_kg = tid & 3;
    const int b_row = tid >> 4, b_cg = tid & 15;

    float acc[4][4];
#pragma unroll
    for (int i = 0; i < 4; i++)
#pragma unroll
        for (int j = 0; j < 4; j++) acc[i][j] = 0.f;

    for (int k0 = 0; k0 < 128; k0 += 16) {
        float4 aw = *(const float4*)(Wm + (o0 + a_row) * 128 + k0 + a_kg * 4);
        As[a_kg * 4 + 0][a_row] = aw.x;
        As[a_kg * 4 + 1][a_row] = aw.y;
        As[a_kg * 4 + 2][a_row] = aw.z;
        As[a_kg * 4 + 3][a_row] = aw.w;
        *(float4*)&Bs[b_row][b_cg * 4] =
            *(const float4*)(Xbase + (size_t)(k0 + b_row) * 4096 + b_cg * 4);
        __syncthreads();
#pragma unroll
        for (int kk = 0; kk < 16; kk++) {
            float4 a  = *(const float4*)&As[kk][ty * 4];
            float4 bq = *(const float4*)&Bs[kk][tx * 4];
            acc[0][0] += a.x * bq.x; acc[0][1] += a.x * bq.y;
            acc[0][2] += a.x * bq.z; acc[0][3] += a.x * bq.w;
            acc[1][0] += a.y * bq.x; acc[1][1] += a.y * bq.y;
            acc[1][2] += a.y * bq.z; acc[1][3] += a.y * bq.w;
            acc[2][0] += a.z * bq.x; acc[2][1] += a.z * bq.y;
            acc[2][2] += a.z * bq.z; acc[2][3] += a.z * bq.w;
            acc[3][0] += a.w * bq.x; acc[3][1] += a.w * bq.y;
            acc[3][2] += a.w * bq.z; acc[3][3] += a.w * bq.w;
        }
        __syncthreads();
    }

    float* Cp = C + (size_t)(o0 + ty * 4) * NPOS + p0 + tx * 4;
#pragma unroll
    for (int i = 0; i < 4; i++) {
        float4 v = make_float4(acc[i][0], acc[i][1], acc[i][2], acc[i][3]);
        *(float4*)(Cp + (size_t)i * NPOS) = v;
    }
}

// ---------------------------------------------------------------------------
// Stage 2
// ---------------------------------------------------------------------------
#define TILE_H 16
#define TILE_W 32
#define EHE    (TILE_H + 14)   // 30
#define EWE    (TILE_W + 14)   // 46
#define CST    20              // 16 ch + 4 pad -> conflict-free LDS.128

__global__ void __launch_bounds__(512, 1) attn_kernel(
    const float* __restrict__ relh,
    const float* __restrict__ relw,
    float* __restrict__ out)
{
    extern __shared__ float sm[];
    float* Ks = sm;
    float* Vs = sm + EHE * EWE * CST;

    const int bz = blockIdx.z;          // b*8 + g
    const int b  = bz >> 3;
    const int g  = bz & 7;
    const int y0 = blockIdx.y * TILE_H;
    const int x0 = blockIdx.x * TILE_W;
    const int ch0 = g * 16;
    const int tid = threadIdx.x;

    // ---- load extended K/V tiles (zero outside image) ----
    const float* Kbase = g_K + (size_t)ch0 * NPOS + b * 4096;
    const float* Vbase = g_V + (size_t)ch0 * NPOS + b * 4096;
    for (int idx = tid; idx < 16 * EHE * EWE; idx += 512) {
        int row = idx / EWE;            // c*EHE + yy
        int xx  = idx - row * EWE;
        int c   = row / EHE;
        int yy  = row - c * EHE;
        int gy = y0 + yy - 7, gx = x0 + xx - 7;
        float kv = 0.f, vv = 0.f;
        if ((unsigned)gy < (unsigned)HH && (unsigned)gx < (unsigned)WW) {
            int off = c * NPOS + gy * WW + gx;
            kv = Kbase[off];
            vv = Vbase[off];
        }
        int s = (yy * EWE + xx) * CST + c;
        Ks[s] = kv;
        Vs[s] = vv;
    }
    __syncthreads();

    const int px = tid & 31, py = tid >> 5;
    const int h = y0 + py, w = x0 + px;

    // ---- per-thread query ----
    float q[16];
    const float* Qp = g_Q + (size_t)ch0 * NPOS + b * 4096 + h * WW + w;
#pragma unroll
    for (int c = 0; c < 16; c++) q[c] = Qp[(size_t)c * NPOS];

    // ---- rel bias: g<4 -> rel_h (by dy), g>=4 -> rel_w (by dx) ----
    const bool use_h = (g < 4);
    const float* rel = use_h ? (relh + ch0 * 7) : (relw + (ch0 - 64) * 7);
    float bias[7];
#pragma unroll
    for (int i = 0; i < 7; i++) {
        float s = 0.f;
#pragma unroll
        for (int c = 0; c < 16; c++) s += q[c] * __ldg(&rel[c * 7 + i]);
        bias[i] = s;
    }

    float outv[16];
#pragma unroll
    for (int c = 0; c < 16; c++) outv[c] = 0.f;

    float vacc[16];
    float ssum;

    // ================= branch A: 2D 7x7 window (with rel bias) =============
    ssum = 0.f;
#pragma unroll
    for (int c = 0; c < 16; c++) vacc[c] = 0.f;
#pragma unroll
    for (int dy = 0; dy < 7; dy++) {
#pragma unroll
        for (int dx = 0; dx < 7; dx++) {
            const int p = (py + 4 + dy) * EWE + (px + 4 + dx);
            const float* kp = &Ks[p * CST];
            float l = use_h ? bias[dy] : bias[dx];
#pragma unroll
            for (int c4 = 0; c4 < 4; c4++) {
                float4 k4 = *(const float4*)(kp + c4 * 4);
                l += q[c4 * 4 + 0] * k4.x + q[c4 * 4 + 1] * k4.y +
                     q[c4 * 4 + 2] * k4.z + q[c4 * 4 + 3] * k4.w;
            }
            float e = __expf(l);
            ssum += e;
            const float* vp = &Vs[p * CST];
#pragma unroll
            for (int c4 = 0; c4 < 4; c4++) {
                float4 v4 = *(const float4*)(vp + c4 * 4);
                vacc[c4 * 4 + 0] += e * v4.x;
                vacc[c4 * 4 + 1] += e * v4.y;
                vacc[c4 * 4 + 2] += e * v4.z;
                vacc[c4 * 4 + 3] += e * v4.w;
            }
        }
    }
    {
        float inv = 1.f / ssum;
#pragma unroll
        for (int c = 0; c < 16; c++) outv[c] += vacc[c] * inv;
    }

    // ================= branch B: row window (15 along x) ===================
    ssum = 0.f;
#pragma unroll
    for (int c = 0; c < 16; c++) vacc[c] = 0.f;
#pragma unroll
    for (int j = 0; j < 15; j++) {
        const int p = (py + 7) * EWE + (px + j);
        const float* kp = &Ks[p * CST];
        float l = 0.f;
#pragma unroll
        for (int c4 = 0; c4 < 4; c4++) {
            float4 k4 = *(const float4*)(kp + c4 * 4);
            l += q[c4 * 4 + 0] * k4.x + q[c4 * 4 + 1] * k4.y +
                 q[c4 * 4 + 2] * k4.z + q[c4 * 4 + 3] * k4.w;
        }
        float e = __expf(l);
        ssum += e;
        const float* vp = &Vs[p * CST];
#pragma unroll
        for (int c4 = 0; c4 < 4; c4++) {
            float4 v4 = *(const float4*)(vp + c4 * 4);
            vacc[c4 * 4 + 0] += e * v4.x;
            vacc[c4 * 4 + 1] += e * v4.y;
            vacc[c4 * 4 + 2] += e * v4.z;
            vacc[c4 * 4 + 3] += e * v4.w;
        }
    }
    {
        float inv = 1.f / ssum;
#pragma unroll
        for (int c = 0; c < 16; c++) outv[c] += vacc[c] * inv;
    }

    // ================= branch C: col window (15 along y) ===================
    ssum = 0.f;
#pragma unroll
    for (int c = 0; c < 16; c++) vacc[c] = 0.f;
#pragma unroll
    for (int i = 0; i < 15; i++) {
        const int p = (py + i) * EWE + (px + 7);
        const float* kp = &Ks[p * CST];
        float l = 0.f;
#pragma unroll
        for (int c4 = 0; c4 < 4; c4++) {
            float4 k4 = *(const float4*)(kp + c4 * 4);
            l += q[c4 * 4 + 0] * k4.x + q[c4 * 4 + 1] * k4.y +
                 q[c4 * 4 + 2] * k4.z + q[c4 * 4 + 3] * k4.w;
        }
        float e = __expf(l);
        ssum += e;
        const float* vp = &Vs[p * CST];
#pragma unroll
        for (int c4 = 0; c4 < 4; c4++) {
            float4 v4 = *(const float4*)(vp + c4 * 4);
            vacc[c4 * 4 + 0] += e * v4.x;
            vacc[c4 * 4 + 1] += e * v4.y;
            vacc[c4 * 4 + 2] += e * v4.z;
            vacc[c4 * 4 + 3] += e * v4.w;
        }
    }
    {
        float inv = 1.f / ssum;
#pragma unroll
        for (int c = 0; c < 16; c++) outv[c] += vacc[c] * inv;
    }

    // ---- write output (B, 128, 64, 64) ----
    float* op = out + (size_t)(b * NCH + ch0) * 4096 + h * WW + w;
#pragma unroll
    for (int c = 0; c < 16; c++) op[(size_t)c * 4096] = outv[c];
}

// ---------------------------------------------------------------------------
extern "C" void kernel_launch(void* const* d_in, const int* in_sizes, int n_in,
                              void* d_out, int out_size)
{
    const float* fm   = (const float*)d_in[0];
    const float* wq   = (const float*)d_in[1];
    const float* wk   = (const float*)d_in[2];
    const float* wv   = (const float*)d_in[3];
    const float* relh = (const float*)d_in[4];
    const float* relw = (const float*)d_in[5];
    float* out = (float*)d_out;

    const int smem_bytes = 2 * EHE * EWE * CST * (int)sizeof(float);  // 220800
    cudaFuncSetAttribute(attn_kernel,
                         cudaFuncAttributeMaxDynamicSharedMemorySize, smem_bytes);

    conv_gemm_kernel<<<dim3(NPOS / 64, 2, 3), 256>>>(fm, wq, wk, wv);
    attn_kernel<<<dim3(WW / TILE_W, HH / TILE_H, BB * 8), 512, smem_bytes>>>(
        relh, relw, out);
}

// round 5
// speedup vs baseline: 1.1454x; 1.1454x over previous
#include <cuda_runtime.h>
#include <cstdint>

// ---------------------------------------------------------------------------
// Temporal attention, B=2, H=W=64, C=128, GROUPS=8 (cg=16), K=7, PAD=3, REFINE
// Stage 1: conv1x1 GEMMs (f32x2 packed FMA) -> g_Q, g_K, g_V
// Stage 2: fused windowed attention; row/col branches share the center
//          row/col of the 7x7 window (LDS + dot reuse); f32x2 dot + vacc.
// ---------------------------------------------------------------------------

#define HH   64
#define WW   64
#define BB   2
#define NCH  128
#define NPOS 8192            // BB*HH*WW

__device__ float g_Q[NCH * NPOS];
__device__ float g_K[NCH * NPOS];
__device__ float g_V[NCH * NPOS];

// ---- f32x2 packed helpers -------------------------------------------------
#define MUL_F32X2(out, a, b) \
    asm("mul.rn.f32x2 %0, %1, %2;" : "=l"(out) : "l"(a), "l"(b))
#define ADD_F32X2(out, a, b) \
    asm("add.rn.f32x2 %0, %1, %2;" : "=l"(out) : "l"(a), "l"(b))
#define FMA_F32X2(d, a, b, c) \
    asm("fma.rn.f32x2 %0, %1, %2, %3;" : "=l"(d) : "l"(a), "l"(b), "l"(c))

__device__ __forceinline__ uint64_t pack2(float lo, float hi) {
    uint64_t r;
    asm("mov.b64 %0, {%1, %2};" : "=l"(r)
        : "r"(__float_as_uint(lo)), "r"(__float_as_uint(hi)));
    return r;
}
__device__ __forceinline__ float2 unpack2(uint64_t u) {
    double d = __longlong_as_double((long long)u);
    return make_float2(__int_as_float(__double2loint(d)),
                       __int_as_float(__double2hiint(d)));
}
__device__ __forceinline__ uint64_t d2u(double d) {
    return (uint64_t)__double_as_longlong(d);
}

// ---------------------------------------------------------------------------
// Stage 1: C[o][p] = sum_c W[o][c] * X[c][p]   (z: 0=K,1=V,2=Q)
// A-weights stored DUPLICATED ({a,a} pairs) in smem so f32x2 FMA needs no
// register packing in the inner loop.
// ---------------------------------------------------------------------------
__global__ void __launch_bounds__(256) conv_gemm_kernel(
    const float* __restrict__ fm,
    const float* __restrict__ wq,
    const float* __restrict__ wk,
    const float* __restrict__ wv)
{
    const int z = blockIdx.z;
    const float* Wm = (z == 0) ? wk : (z == 1) ? wv : wq;
    float* C        = (z == 0) ? g_K : (z == 1) ? g_V : g_Q;
    const int cbase = (z == 2) ? 128 : 0;

    const int p0 = blockIdx.x * 64;
    const int o0 = blockIdx.y * 64;
    const int b   = p0 >> 12;
    const int hw0 = p0 & 4095;
    const float* Xbase = fm + (size_t)b * (256 * 4096) + (size_t)cbase * 4096 + hw0;

    __shared__ float As2[16][132];    // [k][o*2] duplicated pairs (row 528B)
    __shared__ float Bs[16][64];

    const int tid  = threadIdx.x;
    const int tx   = tid & 15;
    const int ty   = tid >> 4;
    const int a_row = tid >> 2, a_kg = tid & 3;
    const int b_row = tid >> 4, b_cg = tid & 15;

    uint64_t accp[4][2];              // [i][j-pair], packed f32x2
#pragma unroll
    for (int i = 0; i < 4; i++) { accp[i][0] = 0ull; accp[i][1] = 0ull; }

    for (int k0 = 0; k0 < 128; k0 += 16) {
        float4 aw = *(const float4*)(Wm + (o0 + a_row) * 128 + k0 + a_kg * 4);
        {   // duplicated STS.64 stores
            uint64_t t;
            t = pack2(aw.x, aw.x);
            *(uint64_t*)&As2[a_kg * 4 + 0][a_row * 2] = t;
            t = pack2(aw.y, aw.y);
            *(uint64_t*)&As2[a_kg * 4 + 1][a_row * 2] = t;
            t = pack2(aw.z, aw.z);
            *(uint64_t*)&As2[a_kg * 4 + 2][a_row * 2] = t;
            t = pack2(aw.w, aw.w);
            *(uint64_t*)&As2[a_kg * 4 + 3][a_row * 2] = t;
        }
        *(float4*)&Bs[b_row][b_cg * 4] =
            *(const float4*)(Xbase + (size_t)(k0 + b_row) * 4096 + b_cg * 4);
        __syncthreads();
#pragma unroll
        for (int kk = 0; kk < 16; kk++) {
            const double2* ad = (const double2*)&As2[kk][ty * 8];
            double2 aA = ad[0], aB = ad[1];
            uint64_t a0 = d2u(aA.x), a1 = d2u(aA.y);
            uint64_t a2 = d2u(aB.x), a3 = d2u(aB.y);
            double2 bv = *(const double2*)&Bs[kk][tx * 4];
            uint64_t b01 = d2u(bv.x), b23 = d2u(bv.y);
            FMA_F32X2(accp[0][0], a0, b01, accp[0][0]);
            FMA_F32X2(accp[0][1], a0, b23, accp[0][1]);
            FMA_F32X2(accp[1][0], a1, b01, accp[1][0]);
            FMA_F32X2(accp[1][1], a1, b23, accp[1][1]);
            FMA_F32X2(accp[2][0], a2, b01, accp[2][0]);
            FMA_F32X2(accp[2][1], a2, b23, accp[2][1]);
            FMA_F32X2(accp[3][0], a3, b01, accp[3][0]);
            FMA_F32X2(accp[3][1], a3, b23, accp[3][1]);
        }
        __syncthreads();
    }

    float* Cp = C + (size_t)(o0 + ty * 4) * NPOS + p0 + tx * 4;
#pragma unroll
    for (int i = 0; i < 4; i++) {
        float2 u0 = unpack2(accp[i][0]);
        float2 u1 = unpack2(accp[i][1]);
        float4 v = make_float4(u0.x, u0.y, u1.x, u1.y);
        *(float4*)(Cp + (size_t)i * NPOS) = v;
    }
}

// ---------------------------------------------------------------------------
// Stage 2
// ---------------------------------------------------------------------------
#define TILE_H 16
#define TILE_W 32
#define EHE    (TILE_H + 14)   // 30
#define EWE    (TILE_W + 14)   // 46
#define CST    20              // 16 ch + 4 pad -> conflict-free LDS.128

// 16-channel dot: K as packed double2 (LDS.128), q pre-packed pairs.
__device__ __forceinline__ float dot16(const float* kp, const uint64_t* qp)
{
    const double2* kd = (const double2*)kp;
    double2 k01 = kd[0], k23 = kd[1], k45 = kd[2], k67 = kd[3];
    uint64_t d0, d1;
    MUL_F32X2(d0, qp[0], d2u(k01.x));
    MUL_F32X2(d1, qp[1], d2u(k01.y));
    FMA_F32X2(d0, qp[2], d2u(k23.x), d0);
    FMA_F32X2(d1, qp[3], d2u(k23.y), d1);
    FMA_F32X2(d0, qp[4], d2u(k45.x), d0);
    FMA_F32X2(d1, qp[5], d2u(k45.y), d1);
    FMA_F32X2(d0, qp[6], d2u(k67.x), d0);
    FMA_F32X2(d1, qp[7], d2u(k67.y), d1);
    ADD_F32X2(d0, d0, d1);
    float2 f = unpack2(d0);
    return f.x + f.y;
}

// vacc[0..7] (packed pairs) += {e,e} * V[0..15]
__device__ __forceinline__ void accv8(uint64_t* acc, const float* vp, uint64_t ep)
{
    const double2* vd = (const double2*)vp;
#pragma unroll
    for (int j = 0; j < 4; j++) {
        double2 v = vd[j];
        uint64_t va = d2u(v.x), vb = d2u(v.y);
        FMA_F32X2(acc[2 * j],     ep, va, acc[2 * j]);
        FMA_F32X2(acc[2 * j + 1], ep, vb, acc[2 * j + 1]);
    }
}

__global__ void __launch_bounds__(512, 1) attn_kernel(
    const float* __restrict__ relh,
    const float* __restrict__ relw,
    float* __restrict__ out)
{
    extern __shared__ float sm[];
    float* Ks = sm;
    float* Vs = sm + EHE * EWE * CST;

    const int bz = blockIdx.z;          // b*8 + g
    const int b  = bz >> 3;
    const int g  = bz & 7;
    const int y0 = blockIdx.y * TILE_H;
    const int x0 = blockIdx.x * TILE_W;
    const int ch0 = g * 16;
    const int tid = threadIdx.x;

    // ---- load extended K/V tiles (zero outside image) ----
    const float* Kbase = g_K + (size_t)ch0 * NPOS + b * 4096;
    const float* Vbase = g_V + (size_t)ch0 * NPOS + b * 4096;
    for (int idx = tid; idx < 16 * EHE * EWE; idx += 512) {
        int row = idx / EWE;            // c*EHE + yy
        int xx  = idx - row * EWE;
        int c   = row / EHE;
        int yy  = row - c * EHE;
        int gy = y0 + yy - 7, gx = x0 + xx - 7;
        float kv = 0.f, vv = 0.f;
        if ((unsigned)gy < (unsigned)HH && (unsigned)gx < (unsigned)WW) {
            int off = c * NPOS + gy * WW + gx;
            kv = Kbase[off];
            vv = Vbase[off];
        }
        int s = (yy * EWE + xx) * CST + c;
        Ks[s] = kv;
        Vs[s] = vv;
    }
    __syncthreads();

    const int px = tid & 31, py = tid >> 5;
    const int h = y0 + py, w = x0 + px;

    // ---- per-thread query ----
    float q[16];
    const float* Qp = g_Q + (size_t)ch0 * NPOS + b * 4096 + h * WW + w;
#pragma unroll
    for (int c = 0; c < 16; c++) q[c] = Qp[(size_t)c * NPOS];

    // ---- rel bias: g<4 -> rel_h (by dy), g>=4 -> rel_w (by dx) ----
    const bool use_h = (g < 4);
    const float* rel = use_h ? (relh + ch0 * 7) : (relw + (ch0 - 64) * 7);
    float bias[7];
#pragma unroll
    for (int i = 0; i < 7; i++) {
        float s = 0.f;
#pragma unroll
        for (int c = 0; c < 16; c++) s += q[c] * __ldg(&rel[c * 7 + i]);
        bias[i] = s;
    }

    // pack q pairs
    uint64_t qp[8];
#pragma unroll
    for (int j = 0; j < 8; j++) qp[j] = pack2(q[2 * j], q[2 * j + 1]);

    float sA = 0.f, sR = 0.f, sC = 0.f;
    uint64_t vA[8], vR[8], vC[8];
#pragma unroll
    for (int j = 0; j < 8; j++) { vA[j] = 0ull; vR[j] = 0ull; vC[j] = 0ull; }

    // ===== 2D 7x7 window; dy==3 also feeds row branch, dx==3 col branch ====
#pragma unroll
    for (int dy = 0; dy < 7; dy++) {
#pragma unroll
        for (int dx = 0; dx < 7; dx++) {
            const int p = (py + 4 + dy) * EWE + (px + 4 + dx);
            const float* kp = &Ks[p * CST];
            const float* vp = &Vs[p * CST];
            float d = dot16(kp, qp);
            float eA = __expf(d + (use_h ? bias[dy] : bias[dx]));
            sA += eA;
            accv8(vA, vp, pack2(eA, eA));
            if (dy == 3) {              // row window j = 4+dx
                float eR = __expf(d);
                sR += eR;
                accv8(vR, vp, pack2(eR, eR));
            }
            if (dx == 3) {              // col window i = 4+dy
                float eC = __expf(d);
                sC += eC;
                accv8(vC, vp, pack2(eC, eC));
            }
        }
    }

    // ===== remaining row positions j in {0..3, 11..14} =====
#pragma unroll
    for (int t = 0; t < 8; t++) {
        const int j = (t < 4) ? t : (t + 7);
        const int p = (py + 7) * EWE + (px + j);
        float d = dot16(&Ks[p * CST], qp);
        float eR = __expf(d);
        sR += eR;
        accv8(vR, &Vs[p * CST], pack2(eR, eR));
    }
    // ===== remaining col positions i in {0..3, 11..14} =====
#pragma unroll
    for (int t = 0; t < 8; t++) {
        const int i = (t < 4) ? t : (t + 7);
        const int p = (py + i) * EWE + (px + 7);
        float d = dot16(&Ks[p * CST], qp);
        float eC = __expf(d);
        sC += eC;
        accv8(vC, &Vs[p * CST], pack2(eC, eC));
    }

    // ---- combine and write output (B, 128, 64, 64) ----
    const float invA = 1.f / sA, invR = 1.f / sR, invC = 1.f / sC;
    float* op = out + (size_t)(b * NCH + ch0) * 4096 + h * WW + w;
#pragma unroll
    for (int j = 0; j < 8; j++) {
        float2 a = unpack2(vA[j]);
        float2 r = unpack2(vR[j]);
        float2 c = unpack2(vC[j]);
        op[(size_t)(2 * j) * 4096]     = a.x * invA + r.x * invR + c.x * invC;
        op[(size_t)(2 * j + 1) * 4096] = a.y * invA + r.y * invR + c.y * invC;
    }
}

// ---------------------------------------------------------------------------
extern "C" void kernel_launch(void* const* d_in, const int* in_sizes, int n_in,
                              void* d_out, int out_size)
{
    const float* fm   = (const float*)d_in[0];
    const float* wq   = (const float*)d_in[1];
    const float* wk   = (const float*)d_in[2];
    const float* wv   = (const float*)d_in[3];
    const float* relh = (const float*)d_in[4];
    const float* relw = (const float*)d_in[5];
    float* out = (float*)d_out;

    const int smem_bytes = 2 * EHE * EWE * CST * (int)sizeof(float);  // 220800
    cudaFuncSetAttribute(attn_kernel,
                         cudaFuncAttributeMaxDynamicSharedMemorySize, smem_bytes);

    conv_gemm_kernel<<<dim3(NPOS / 64, 2, 3), 256>>>(fm, wq, wk, wv);
    attn_kernel<<<dim3(WW / TILE_W, HH / TILE_H, BB * 8), 512, smem_bytes>>>(
        relh, relw, out);
}

// round 6
// speedup vs baseline: 1.1639x; 1.0161x over previous
#include <cuda_runtime.h>
#include <cstdint>

// ---------------------------------------------------------------------------
// Temporal attention, B=2, H=W=64, C=128, GROUPS=8 (cg=16), K=7, PAD=3, REFINE
// Stage 1: conv1x1 GEMM, 128x128 tile, 8x8/thread, f32x2, 1 byte/MAC LDS.
// Stage 2: fused windowed attention, channel-split 2 threads/position,
//          8x16 tile / 256 threads / 2 blocks per SM.
// ---------------------------------------------------------------------------

#define HH   64
#define WW   64
#define BB   2
#define NCH  128
#define NPOS 8192            // BB*HH*WW

__device__ float g_Q[NCH * NPOS];
__device__ float g_K[NCH * NPOS];
__device__ float g_V[NCH * NPOS];

// ---- f32x2 packed helpers -------------------------------------------------
#define MUL_F32X2(out, a, b) \
    asm("mul.rn.f32x2 %0, %1, %2;" : "=l"(out) : "l"(a), "l"(b))
#define ADD_F32X2(out, a, b) \
    asm("add.rn.f32x2 %0, %1, %2;" : "=l"(out) : "l"(a), "l"(b))
#define FMA_F32X2(d, a, b, c) \
    asm("fma.rn.f32x2 %0, %1, %2, %3;" : "=l"(d) : "l"(a), "l"(b), "l"(c))

__device__ __forceinline__ uint64_t pack2(float lo, float hi) {
    uint64_t r;
    asm("mov.b64 %0, {%1, %2};" : "=l"(r)
        : "r"(__float_as_uint(lo)), "r"(__float_as_uint(hi)));
    return r;
}
__device__ __forceinline__ float2 unpack2(uint64_t u) {
    double d = __longlong_as_double((long long)u);
    return make_float2(__int_as_float(__double2loint(d)),
                       __int_as_float(__double2hiint(d)));
}
__device__ __forceinline__ uint64_t d2u(double d) {
    return (uint64_t)__double_as_longlong(d);
}

// ---------------------------------------------------------------------------
// Stage 1: C[o][p] = sum_c W[o][c] * X[c][p]   (z: 0=K,1=V,2=Q)
// Block: 128 o x 128 p, 256 threads, thread tile 8x8 (rows {ty*4..+3, 64+..},
// cols {tx*4..+3, 64+..}).  Plain smem tiles; A duplicated in registers.
// ---------------------------------------------------------------------------
__global__ void __launch_bounds__(256, 2) conv_gemm_kernel(
    const float* __restrict__ fm,
    const float* __restrict__ wq,
    const float* __restrict__ wk,
    const float* __restrict__ wv)
{
    const int z = blockIdx.y;
    const float* Wm = (z == 0) ? wk : (z == 1) ? wv : wq;
    float* C        = (z == 0) ? g_K : (z == 1) ? g_V : g_Q;
    const int cbase = (z == 2) ? 128 : 0;

    const int p0  = blockIdx.x * 128;
    const int b   = p0 >> 12;
    const int hw0 = p0 & 4095;
    const float* Xbase = fm + (size_t)b * (256 * 4096) + (size_t)cbase * 4096 + hw0;

    __shared__ float As[16][128];     // [k][o]
    __shared__ float Bs[16][128];     // [k][p]

    const int tid = threadIdx.x;
    const int tx  = tid & 15;
    const int ty  = tid >> 4;

    // loader roles
    const int ao = tid >> 1;          // o row 0..127
    const int akq = (tid & 1) * 8;    // k sub-offset 0 or 8
    const int bkr = tid >> 4;         // k row 0..15
    const int bpc = (tid & 15) * 8;   // p col

    uint64_t acc[8][4];
#pragma unroll
    for (int r = 0; r < 8; r++)
#pragma unroll
        for (int c = 0; c < 4; c++) acc[r][c] = 0ull;

    // prefetch tile 0
    float4 af0 = *(const float4*)(Wm + ao * 128 + akq);
    float4 af1 = *(const float4*)(Wm + ao * 128 + akq + 4);
    float4 bf0 = *(const float4*)(Xbase + (size_t)bkr * 4096 + bpc);
    float4 bf1 = *(const float4*)(Xbase + (size_t)bkr * 4096 + bpc + 4);

    for (int k0 = 0; k0 < 128; k0 += 16) {
        As[akq + 0][ao] = af0.x; As[akq + 1][ao] = af0.y;
        As[akq + 2][ao] = af0.z; As[akq + 3][ao] = af0.w;
        As[akq + 4][ao] = af1.x; As[akq + 5][ao] = af1.y;
        As[akq + 6][ao] = af1.z; As[akq + 7][ao] = af1.w;
        *(float4*)&Bs[bkr][bpc]     = bf0;
        *(float4*)&Bs[bkr][bpc + 4] = bf1;
        __syncthreads();

        if (k0 < 112) {
            af0 = *(const float4*)(Wm + ao * 128 + k0 + 16 + akq);
            af1 = *(const float4*)(Wm + ao * 128 + k0 + 16 + akq + 4);
            bf0 = *(const float4*)(Xbase + (size_t)(k0 + 16 + bkr) * 4096 + bpc);
            bf1 = *(const float4*)(Xbase + (size_t)(k0 + 16 + bkr) * 4096 + bpc + 4);
        }

#pragma unroll
        for (int kk = 0; kk < 16; kk++) {
            float4 a0 = *(const float4*)&As[kk][ty * 4];
            float4 a1 = *(const float4*)&As[kk][64 + ty * 4];
            float4 b0 = *(const float4*)&Bs[kk][tx * 4];
            float4 b1 = *(const float4*)&Bs[kk][64 + tx * 4];
            uint64_t bp0 = pack2(b0.x, b0.y), bp1 = pack2(b0.z, b0.w);
            uint64_t bp2 = pack2(b1.x, b1.y), bp3 = pack2(b1.z, b1.w);
            uint64_t ad;
            ad = pack2(a0.x, a0.x);
            FMA_F32X2(acc[0][0], ad, bp0, acc[0][0]);
            FMA_F32X2(acc[0][1], ad, bp1, acc[0][1]);
            FMA_F32X2(acc[0][2], ad, bp2, acc[0][2]);
            FMA_F32X2(acc[0][3], ad, bp3, acc[0][3]);
            ad = pack2(a0.y, a0.y);
            FMA_F32X2(acc[1][0], ad, bp0, acc[1][0]);
            FMA_F32X2(acc[1][1], ad, bp1, acc[1][1]);
            FMA_F32X2(acc[1][2], ad, bp2, acc[1][2]);
            FMA_F32X2(acc[1][3], ad, bp3, acc[1][3]);
            ad = pack2(a0.z, a0.z);
            FMA_F32X2(acc[2][0], ad, bp0, acc[2][0]);
            FMA_F32X2(acc[2][1], ad, bp1, acc[2][1]);
            FMA_F32X2(acc[2][2], ad, bp2, acc[2][2]);
            FMA_F32X2(acc[2][3], ad, bp3, acc[2][3]);
            ad = pack2(a0.w, a0.w);
            FMA_F32X2(acc[3][0], ad, bp0, acc[3][0]);
            FMA_F32X2(acc[3][1], ad, bp1, acc[3][1]);
            FMA_F32X2(acc[3][2], ad, bp2, acc[3][2]);
            FMA_F32X2(acc[3][3], ad, bp3, acc[3][3]);
            ad = pack2(a1.x, a1.x);
            FMA_F32X2(acc[4][0], ad, bp0, acc[4][0]);
            FMA_F32X2(acc[4][1], ad, bp1, acc[4][1]);
            FMA_F32X2(acc[4][2], ad, bp2, acc[4][2]);
            FMA_F32X2(acc[4][3], ad, bp3, acc[4][3]);
            ad = pack2(a1.y, a1.y);
            FMA_F32X2(acc[5][0], ad, bp0, acc[5][0]);
            FMA_F32X2(acc[5][1], ad, bp1, acc[5][1]);
            FMA_F32X2(acc[5][2], ad, bp2, acc[5][2]);
            FMA_F32X2(acc[5][3], ad, bp3, acc[5][3]);
            ad = pack2(a1.z, a1.z);
            FMA_F32X2(acc[6][0], ad, bp0, acc[6][0]);
            FMA_F32X2(acc[6][1], ad, bp1, acc[6][1]);
            FMA_F32X2(acc[6][2], ad, bp2, acc[6][2]);
            FMA_F32X2(acc[6][3], ad, bp3, acc[6][3]);
            ad = pack2(a1.w, a1.w);
            FMA_F32X2(acc[7][0], ad, bp0, acc[7][0]);
            FMA_F32X2(acc[7][1], ad, bp1, acc[7][1]);
            FMA_F32X2(acc[7][2], ad, bp2, acc[7][2]);
            FMA_F32X2(acc[7][3], ad, bp3, acc[7][3]);
        }
        __syncthreads();
    }

#pragma unroll
    for (int r = 0; r < 8; r++) {
        const int o = (r < 4) ? (ty * 4 + r) : (64 + ty * 4 + (r - 4));
        float2 u0 = unpack2(acc[r][0]);
        float2 u1 = unpack2(acc[r][1]);
        float2 u2 = unpack2(acc[r][2]);
        float2 u3 = unpack2(acc[r][3]);
        float* Cp = C + (size_t)o * NPOS + p0;
        *(float4*)(Cp + tx * 4)      = make_float4(u0.x, u0.y, u1.x, u1.y);
        *(float4*)(Cp + 64 + tx * 4) = make_float4(u2.x, u2.y, u3.x, u3.y);
    }
}

// ---------------------------------------------------------------------------
// Stage 2: channel-split attention.
// Block: 256 threads, tile 8x16 positions, 2 threads per position (8 ch each).
// Lane map: half = (tid>>4)&1, pos = (tid&15) | ((tid>>5)<<4)  -> each 8-lane
// LDS phase has uniform half => stride-80B addresses stay conflict-free.
// ---------------------------------------------------------------------------
#define ATH  8
#define ATW  16
#define AEH  (ATH + 14)   // 22
#define AEW  (ATW + 14)   // 30
#define ACST 20           // 16 ch + 4 pad
#define AELEMS (AEH * AEW * ACST)   // 13200 floats

__device__ __forceinline__ float dot8(const float* kp, const uint64_t* qp)
{
    const double2* kd = (const double2*)kp;
    double2 kA = kd[0], kB = kd[1];
    uint64_t d0, d1;
    MUL_F32X2(d0, qp[0], d2u(kA.x));
    MUL_F32X2(d1, qp[1], d2u(kA.y));
    FMA_F32X2(d0, qp[2], d2u(kB.x), d0);
    FMA_F32X2(d1, qp[3], d2u(kB.y), d1);
    ADD_F32X2(d0, d0, d1);
    float2 f = unpack2(d0);
    return f.x + f.y;
}

__device__ __forceinline__ void accv4(uint64_t* acc, const float* vp, uint64_t ep)
{
    const double2* vd = (const double2*)vp;
    double2 vA = vd[0], vB = vd[1];
    FMA_F32X2(acc[0], ep, d2u(vA.x), acc[0]);
    FMA_F32X2(acc[1], ep, d2u(vA.y), acc[1]);
    FMA_F32X2(acc[2], ep, d2u(vB.x), acc[2]);
    FMA_F32X2(acc[3], ep, d2u(vB.y), acc[3]);
}

__global__ void __launch_bounds__(256, 2) attn_kernel(
    const float* __restrict__ relh,
    const float* __restrict__ relw,
    float* __restrict__ out)
{
    extern __shared__ float sm[];
    float* Ks = sm;
    float* Vs = sm + AELEMS;

    const int bz = blockIdx.z;          // b*8 + g
    const int b  = bz >> 3;
    const int g  = bz & 7;
    const int y0 = blockIdx.y * ATH;
    const int x0 = blockIdx.x * ATW;
    const int ch0 = g * 16;
    const int tid = threadIdx.x;

    // ---- load extended K/V tiles (zero outside image) ----
    const float* Kbase = g_K + (size_t)ch0 * NPOS + b * 4096;
    const float* Vbase = g_V + (size_t)ch0 * NPOS + b * 4096;
    for (int idx = tid; idx < 16 * AEH * AEW; idx += 256) {
        int c   = idx / (AEH * AEW);
        int rem = idx - c * (AEH * AEW);
        int yy  = rem / AEW;
        int xx  = rem - yy * AEW;
        int gy = y0 + yy - 7, gx = x0 + xx - 7;
        float kv = 0.f, vv = 0.f;
        if ((unsigned)gy < (unsigned)HH && (unsigned)gx < (unsigned)WW) {
            int off = c * NPOS + gy * WW + gx;
            kv = Kbase[off];
            vv = Vbase[off];
        }
        int s = (yy * AEW + xx) * ACST + c;
        Ks[s] = kv;
        Vs[s] = vv;
    }
    __syncthreads();

    const int half = (tid >> 4) & 1;
    const int pos  = (tid & 15) | ((tid >> 5) << 4);  // 0..127
    const int px = pos & 15, py = pos >> 4;
    const int h = y0 + py, w = x0 + px;
    const int co = half * 8;

    // ---- per-thread half query (8 channels) ----
    float q[8];
    const float* Qp = g_Q + (size_t)(ch0 + co) * NPOS + b * 4096 + h * WW + w;
#pragma unroll
    for (int c = 0; c < 8; c++) q[c] = Qp[(size_t)c * NPOS];
    uint64_t qp[4];
#pragma unroll
    for (int j = 0; j < 4; j++) qp[j] = pack2(q[2 * j], q[2 * j + 1]);

    // ---- rel bias (full over 16 ch via shfl), exponentiated ----
    const bool use_h = (g < 4);
    const float* rel = use_h ? (relh + (ch0 + co) * 7) : (relw + (ch0 - 64 + co) * 7);
    float eb[7];
#pragma unroll
    for (int i = 0; i < 7; i++) {
        float s = 0.f;
#pragma unroll
        for (int c = 0; c < 8; c++) s += q[c] * __ldg(&rel[c * 7 + i]);
        s += __shfl_xor_sync(0xffffffffu, s, 16);
        eb[i] = __expf(s);
    }

    float sA = 0.f, sR = 0.f, sC = 0.f;
    uint64_t vA[4], vR[4], vC[4];
#pragma unroll
    for (int j = 0; j < 4; j++) { vA[j] = 0ull; vR[j] = 0ull; vC[j] = 0ull; }

    // ===== 2D 7x7 window; dy==3 feeds row branch, dx==3 col branch =========
#pragma unroll
    for (int dy = 0; dy < 7; dy++) {
#pragma unroll
        for (int dx = 0; dx < 7; dx++) {
            const int p = (py + 4 + dy) * AEW + (px + 4 + dx);
            const float* kp = &Ks[p * ACST + co];
            const float* vp = &Vs[p * ACST + co];
            float dp = dot8(kp, qp);
            float d  = dp + __shfl_xor_sync(0xffffffffu, dp, 16);
            float ed = __expf(d);
            float eA = ed * eb[use_h ? dy : dx];
            sA += eA;
            accv4(vA, vp, pack2(eA, eA));
            if (dy == 3) { sR += ed; accv4(vR, vp, pack2(ed, ed)); }
            if (dx == 3) { sC += ed; accv4(vC, vp, pack2(ed, ed)); }
        }
    }

    // ===== remaining row positions j in {0..3, 11..14} =====
#pragma unroll
    for (int t = 0; t < 8; t++) {
        const int j = (t < 4) ? t : (t + 7);
        const int p = (py + 7) * AEW + (px + j);
        float dp = dot8(&Ks[p * ACST + co], qp);
        float d  = dp + __shfl_xor_sync(0xffffffffu, dp, 16);
        float ed = __expf(d);
        sR += ed;
        accv4(vR, &Vs[p * ACST + co], pack2(ed, ed));
    }
    // ===== remaining col positions i in {0..3, 11..14} =====
#pragma unroll
    for (int t = 0; t < 8; t++) {
        const int i = (t < 4) ? t : (t + 7);
        const int p = (py + i) * AEW + (px + 7);
        float dp = dot8(&Ks[p * ACST + co], qp);
        float d  = dp + __shfl_xor_sync(0xffffffffu, dp, 16);
        float ed = __expf(d);
        sC += ed;
        accv4(vC, &Vs[p * ACST + co], pack2(ed, ed));
    }

    // ---- combine and write output (B, 128, 64, 64), own 8 channels ----
    const float invA = 1.f / sA, invR = 1.f / sR, invC = 1.f / sC;
    float* op = out + (size_t)(b * NCH + ch0 + co) * 4096 + h * WW + w;
#pragma unroll
    for (int j = 0; j < 4; j++) {
        float2 a = unpack2(vA[j]);
        float2 r = unpack2(vR[j]);
        float2 c = unpack2(vC[j]);
        op[(size_t)(2 * j) * 4096]     = a.x * invA + r.x * invR + c.x * invC;
        op[(size_t)(2 * j + 1) * 4096] = a.y * invA + r.y * invR + c.y * invC;
    }
}

// ---------------------------------------------------------------------------
extern "C" void kernel_launch(void* const* d_in, const int* in_sizes, int n_in,
                              void* d_out, int out_size)
{
    const float* fm   = (const float*)d_in[0];
    const float* wq   = (const float*)d_in[1];
    const float* wk   = (const float*)d_in[2];
    const float* wv   = (const float*)d_in[3];
    const float* relh = (const float*)d_in[4];
    const float* relw = (const float*)d_in[5];
    float* out = (float*)d_out;

    const int smem_bytes = 2 * AELEMS * (int)sizeof(float);  // 105600
    cudaFuncSetAttribute(attn_kernel,
                         cudaFuncAttributeMaxDynamicSharedMemorySize, smem_bytes);

    conv_gemm_kernel<<<dim3(NPOS / 128, 3), 256>>>(fm, wq, wk, wv);
    attn_kernel<<<dim3(WW / ATW, HH / ATH, BB * 8), 256, smem_bytes>>>(
        relh, relw, out);
}

// round 8
// speedup vs baseline: 1.3673x; 1.1748x over previous
#include <cuda_runtime.h>
#include <cstdint>

// ---------------------------------------------------------------------------
// Temporal attention, B=2, H=W=64, C=128, GROUPS=8 (cg=16), K=7, PAD=3, REFINE
// Stage 1: conv1x1 GEMM, 64o x 128p blocks (384 total -> balanced 3/SM max),
//          128 threads, 8x8/thread, f32x2.
// Stage 2: fused windowed attention, 16x32 tile / 512 threads, f32x2,
//          exp(d+bias) factored as exp(d)*exp(bias) -> 1 MUFU/position.
// ---------------------------------------------------------------------------

#define HH   64
#define WW   64
#define BB   2
#define NCH  128
#define NPOS 8192            // BB*HH*WW

__device__ float g_Q[NCH * NPOS];
__device__ float g_K[NCH * NPOS];
__device__ float g_V[NCH * NPOS];

// ---- f32x2 packed helpers -------------------------------------------------
#define MUL_F32X2(out, a, b) \
    asm("mul.rn.f32x2 %0, %1, %2;" : "=l"(out) : "l"(a), "l"(b))
#define ADD_F32X2(out, a, b) \
    asm("add.rn.f32x2 %0, %1, %2;" : "=l"(out) : "l"(a), "l"(b))
#define FMA_F32X2(d, a, b, c) \
    asm("fma.rn.f32x2 %0, %1, %2, %3;" : "=l"(d) : "l"(a), "l"(b), "l"(c))

__device__ __forceinline__ uint64_t pack2(float lo, float hi) {
    uint64_t r;
    asm("mov.b64 %0, {%1, %2};" : "=l"(r)
        : "r"(__float_as_uint(lo)), "r"(__float_as_uint(hi)));
    return r;
}
__device__ __forceinline__ float2 unpack2(uint64_t u) {
    double d = __longlong_as_double((long long)u);
    return make_float2(__int_as_float(__double2loint(d)),
                       __int_as_float(__double2hiint(d)));
}
__device__ __forceinline__ uint64_t d2u(double d) {
    return (uint64_t)__double_as_longlong(d);
}

// ---------------------------------------------------------------------------
// Stage 1: C[o][p] = sum_c W[o][c] * X[c][p]
// Block: 64 o x 128 p, 128 threads, thread tile 8x8
//   rows: {o0 + ty*4 .. +3, o0 + 32 + ty*4 .. +3}, ty = tid>>4 (0..7)
//   cols: {p0 + tx*4 .. +3, p0 + 64 + tx*4 .. +3}, tx = tid&15
// Grid: (64 p-tiles, 2 o-tiles, 3 matrices) = 384 blocks.
// ---------------------------------------------------------------------------
__global__ void __launch_bounds__(128, 3) conv_gemm_kernel(
    const float* __restrict__ fm,
    const float* __restrict__ wq,
    const float* __restrict__ wk,
    const float* __restrict__ wv)
{
    const int z = blockIdx.z;
    const float* Wm = (z == 0) ? wk : (z == 1) ? wv : wq;
    float* C        = (z == 0) ? g_K : (z == 1) ? g_V : g_Q;
    const int cbase = (z == 2) ? 128 : 0;

    const int p0  = blockIdx.x * 128;
    const int o0  = blockIdx.y * 64;
    const int b   = p0 >> 12;
    const int hw0 = p0 & 4095;
    const float* Xbase = fm + (size_t)b * (256 * 4096) + (size_t)cbase * 4096 + hw0;

    __shared__ float As[16][64];      // [k][o]
    __shared__ float Bs[16][128];     // [k][p]

    const int tid = threadIdx.x;
    const int tx  = tid & 15;
    const int ty  = tid >> 4;         // 0..7

    // loader roles
    const int ao  = tid >> 1;         // o row 0..63
    const int akq = (tid & 1) * 8;    // k sub-offset 0 or 8
    const int bkr = tid >> 3;         // k row 0..15
    const int bpc = (tid & 7) * 16;   // p col, 16 floats per thread

    uint64_t acc[8][4];
#pragma unroll
    for (int r = 0; r < 8; r++)
#pragma unroll
        for (int c = 0; c < 4; c++) acc[r][c] = 0ull;

    // prefetch tile 0
    float4 af0 = *(const float4*)(Wm + (o0 + ao) * 128 + akq);
    float4 af1 = *(const float4*)(Wm + (o0 + ao) * 128 + akq + 4);
    float4 bf0 = *(const float4*)(Xbase + (size_t)bkr * 4096 + bpc);
    float4 bf1 = *(const float4*)(Xbase + (size_t)bkr * 4096 + bpc + 4);
    float4 bf2 = *(const float4*)(Xbase + (size_t)bkr * 4096 + bpc + 8);
    float4 bf3 = *(const float4*)(Xbase + (size_t)bkr * 4096 + bpc + 12);

    for (int k0 = 0; k0 < 128; k0 += 16) {
        As[akq + 0][ao] = af0.x; As[akq + 1][ao] = af0.y;
        As[akq + 2][ao] = af0.z; As[akq + 3][ao] = af0.w;
        As[akq + 4][ao] = af1.x; As[akq + 5][ao] = af1.y;
        As[akq + 6][ao] = af1.z; As[akq + 7][ao] = af1.w;
        *(float4*)&Bs[bkr][bpc]      = bf0;
        *(float4*)&Bs[bkr][bpc + 4]  = bf1;
        *(float4*)&Bs[bkr][bpc + 8]  = bf2;
        *(float4*)&Bs[bkr][bpc + 12] = bf3;
        __syncthreads();

        if (k0 < 112) {
            af0 = *(const float4*)(Wm + (o0 + ao) * 128 + k0 + 16 + akq);
            af1 = *(const float4*)(Wm + (o0 + ao) * 128 + k0 + 16 + akq + 4);
            const float* Xn = Xbase + (size_t)(k0 + 16 + bkr) * 4096 + bpc;
            bf0 = *(const float4*)(Xn);
            bf1 = *(const float4*)(Xn + 4);
            bf2 = *(const float4*)(Xn + 8);
            bf3 = *(const float4*)(Xn + 12);
        }

#pragma unroll
        for (int kk = 0; kk < 16; kk++) {
            float4 a0 = *(const float4*)&As[kk][ty * 4];
            float4 a1 = *(const float4*)&As[kk][32 + ty * 4];
            float4 b0 = *(const float4*)&Bs[kk][tx * 4];
            float4 b1 = *(const float4*)&Bs[kk][64 + tx * 4];
            uint64_t bp0 = pack2(b0.x, b0.y), bp1 = pack2(b0.z, b0.w);
            uint64_t bp2 = pack2(b1.x, b1.y), bp3 = pack2(b1.z, b1.w);
            uint64_t ad;
            ad = pack2(a0.x, a0.x);
            FMA_F32X2(acc[0][0], ad, bp0, acc[0][0]);
            FMA_F32X2(acc[0][1], ad, bp1, acc[0][1]);
            FMA_F32X2(acc[0][2], ad, bp2, acc[0][2]);
            FMA_F32X2(acc[0][3], ad, bp3, acc[0][3]);
            ad = pack2(a0.y, a0.y);
            FMA_F32X2(acc[1][0], ad, bp0, acc[1][0]);
            FMA_F32X2(acc[1][1], ad, bp1, acc[1][1]);
            FMA_F32X2(acc[1][2], ad, bp2, acc[1][2]);
            FMA_F32X2(acc[1][3], ad, bp3, acc[1][3]);
            ad = pack2(a0.z, a0.z);
            FMA_F32X2(acc[2][0], ad, bp0, acc[2][0]);
            FMA_F32X2(acc[2][1], ad, bp1, acc[2][1]);
            FMA_F32X2(acc[2][2], ad, bp2, acc[2][2]);
            FMA_F32X2(acc[2][3], ad, bp3, acc[2][3]);
            ad = pack2(a0.w, a0.w);
            FMA_F32X2(acc[3][0], ad, bp0, acc[3][0]);
            FMA_F32X2(acc[3][1], ad, bp1, acc[3][1]);
            FMA_F32X2(acc[3][2], ad, bp2, acc[3][2]);
            FMA_F32X2(acc[3][3], ad, bp3, acc[3][3]);
            ad = pack2(a1.x, a1.x);
            FMA_F32X2(acc[4][0], ad, bp0, acc[4][0]);
            FMA_F32X2(acc[4][1], ad, bp1, acc[4][1]);
            FMA_F32X2(acc[4][2], ad, bp2, acc[4][2]);
            FMA_F32X2(acc[4][3], ad, bp3, acc[4][3]);
            ad = pack2(a1.y, a1.y);
            FMA_F32X2(acc[5][0], ad, bp0, acc[5][0]);
            FMA_F32X2(acc[5][1], ad, bp1, acc[5][1]);
            FMA_F32X2(acc[5][2], ad, bp2, acc[5][2]);
            FMA_F32X2(acc[5][3], ad, bp3, acc[5][3]);
            ad = pack2(a1.z, a1.z);
            FMA_F32X2(acc[6][0], ad, bp0, acc[6][0]);
            FMA_F32X2(acc[6][1], ad, bp1, acc[6][1]);
            FMA_F32X2(acc[6][2], ad, bp2, acc[6][2]);
            FMA_F32X2(acc[6][3], ad, bp3, acc[6][3]);
            ad = pack2(a1.w, a1.w);
            FMA_F32X2(acc[7][0], ad, bp0, acc[7][0]);
            FMA_F32X2(acc[7][1], ad, bp1, acc[7][1]);
            FMA_F32X2(acc[7][2], ad, bp2, acc[7][2]);
            FMA_F32X2(acc[7][3], ad, bp3, acc[7][3]);
        }
        __syncthreads();
    }

#pragma unroll
    for (int r = 0; r < 8; r++) {
        const int o = o0 + ((r < 4) ? (ty * 4 + r) : (32 + ty * 4 + (r - 4)));
        float2 u0 = unpack2(acc[r][0]);
        float2 u1 = unpack2(acc[r][1]);
        float2 u2 = unpack2(acc[r][2]);
        float2 u3 = unpack2(acc[r][3]);
        float* Cp = C + (size_t)o * NPOS + p0;
        *(float4*)(Cp + tx * 4)      = make_float4(u0.x, u0.y, u1.x, u1.y);
        *(float4*)(Cp + 64 + tx * 4) = make_float4(u2.x, u2.y, u3.x, u3.y);
    }
}

// ---------------------------------------------------------------------------
// Stage 2
// ---------------------------------------------------------------------------
#define TILE_H 16
#define TILE_W 32
#define EHE    (TILE_H + 14)   // 30
#define EWE    (TILE_W + 14)   // 46
#define CST    20              // 16 ch + 4 pad -> conflict-free LDS.128

__device__ __forceinline__ float dot16(const float* kp, const uint64_t* qp)
{
    const double2* kd = (const double2*)kp;
    double2 k01 = kd[0], k23 = kd[1], k45 = kd[2], k67 = kd[3];
    uint64_t d0, d1;
    MUL_F32X2(d0, qp[0], d2u(k01.x));
    MUL_F32X2(d1, qp[1], d2u(k01.y));
    FMA_F32X2(d0, qp[2], d2u(k23.x), d0);
    FMA_F32X2(d1, qp[3], d2u(k23.y), d1);
    FMA_F32X2(d0, qp[4], d2u(k45.x), d0);
    FMA_F32X2(d1, qp[5], d2u(k45.y), d1);
    FMA_F32X2(d0, qp[6], d2u(k67.x), d0);
    FMA_F32X2(d1, qp[7], d2u(k67.y), d1);
    ADD_F32X2(d0, d0, d1);
    float2 f = unpack2(d0);
    return f.x + f.y;
}

__device__ __forceinline__ void accv8(uint64_t* acc, const float* vp, uint64_t ep)
{
    const double2* vd = (const double2*)vp;
#pragma unroll
    for (int j = 0; j < 4; j++) {
        double2 v = vd[j];
        uint64_t va = d2u(v.x), vb = d2u(v.y);
        FMA_F32X2(acc[2 * j],     ep, va, acc[2 * j]);
        FMA_F32X2(acc[2 * j + 1], ep, vb, acc[2 * j + 1]);
    }
}

__global__ void __launch_bounds__(512, 1) attn_kernel(
    const float* __restrict__ relh,
    const float* __restrict__ relw,
    float* __restrict__ out)
{
    extern __shared__ float sm[];
    float* Ks = sm;
    float* Vs = sm + EHE * EWE * CST;

    const int bz = blockIdx.z;          // b*8 + g
    const int b  = bz >> 3;
    const int g  = bz & 7;
    const int y0 = blockIdx.y * TILE_H;
    const int x0 = blockIdx.x * TILE_W;
    const int ch0 = g * 16;
    const int tid = threadIdx.x;

    // ---- load extended K/V tiles (zero outside image) ----
    const float* Kbase = g_K + (size_t)ch0 * NPOS + b * 4096;
    const float* Vbase = g_V + (size_t)ch0 * NPOS + b * 4096;
    for (int idx = tid; idx < 16 * EHE * EWE; idx += 512) {
        int row = idx / EWE;            // c*EHE + yy
        int xx  = idx - row * EWE;
        int c   = row / EHE;
        int yy  = row - c * EHE;
        int gy = y0 + yy - 7, gx = x0 + xx - 7;
        float kv = 0.f, vv = 0.f;
        if ((unsigned)gy < (unsigned)HH && (unsigned)gx < (unsigned)WW) {
            int off = c * NPOS + gy * WW + gx;
            kv = Kbase[off];
            vv = Vbase[off];
        }
        int s = (yy * EWE + xx) * CST + c;
        Ks[s] = kv;
        Vs[s] = vv;
    }
    __syncthreads();

    const int px = tid & 31, py = tid >> 5;
    const int h = y0 + py, w = x0 + px;

    // ---- per-thread query ----
    float q[16];
    const float* Qp = g_Q + (size_t)ch0 * NPOS + b * 4096 + h * WW + w;
#pragma unroll
    for (int c = 0; c < 16; c++) q[c] = Qp[(size_t)c * NPOS];

    // ---- rel bias, exponentiated once: g<4 -> rel_h(dy), g>=4 -> rel_w(dx)
    const bool use_h = (g < 4);
    const float* rel = use_h ? (relh + ch0 * 7) : (relw + (ch0 - 64) * 7);
    float eb[7];
#pragma unroll
    for (int i = 0; i < 7; i++) {
        float s = 0.f;
#pragma unroll
        for (int c = 0; c < 16; c++) s += q[c] * __ldg(&rel[c * 7 + i]);
        eb[i] = __expf(s);
    }

    uint64_t qp[8];
#pragma unroll
    for (int j = 0; j < 8; j++) qp[j] = pack2(q[2 * j], q[2 * j + 1]);

    float sA = 0.f, sR = 0.f, sC = 0.f;
    uint64_t vA[8], vR[8], vC[8];
#pragma unroll
    for (int j = 0; j < 8; j++) { vA[j] = 0ull; vR[j] = 0ull; vC[j] = 0ull; }

    // ===== 2D 7x7 window; dy==3 feeds row branch, dx==3 col branch =========
#pragma unroll
    for (int dy = 0; dy < 7; dy++) {
#pragma unroll
        for (int dx = 0; dx < 7; dx++) {
            const int p = (py + 4 + dy) * EWE + (px + 4 + dx);
            const float* kp = &Ks[p * CST];
            const float* vp = &Vs[p * CST];
            float d  = dot16(kp, qp);
            float ed = __expf(d);
            float eA = ed * eb[use_h ? dy : dx];
            sA += eA;
            accv8(vA, vp, pack2(eA, eA));
            if (dy == 3) { sR += ed; accv8(vR, vp, pack2(ed, ed)); }
            if (dx == 3) { sC += ed; accv8(vC, vp, pack2(ed, ed)); }
        }
    }

    // ===== remaining row positions j in {0..3, 11..14} =====
#pragma unroll
    for (int t = 0; t < 8; t++) {
        const int j = (t < 4) ? t : (t + 7);
        const int p = (py + 7) * EWE + (px + j);
        float ed = __expf(dot16(&Ks[p * CST], qp));
        sR += ed;
        accv8(vR, &Vs[p * CST], pack2(ed, ed));
    }
    // ===== remaining col positions i in {0..3, 11..14} =====
#pragma unroll
    for (int t = 0; t < 8; t++) {
        const int i = (t < 4) ? t : (t + 7);
        const int p = (py + i) * EWE + (px + 7);
        float ed = __expf(dot16(&Ks[p * CST], qp));
        sC += ed;
        accv8(vC, &Vs[p * CST], pack2(ed, ed));
    }

    // ---- combine and write output (B, 128, 64, 64) ----
    const float invA = 1.f / sA, invR = 1.f / sR, invC = 1.f / sC;
    float* op = out + (size_t)(b * NCH + ch0) * 4096 + h * WW + w;
#pragma unroll
    for (int j = 0; j < 8; j++) {
        float2 a = unpack2(vA[j]);
        float2 r = unpack2(vR[j]);
        float2 c = unpack2(vC[j]);
        op[(size_t)(2 * j) * 4096]     = a.x * invA + r.x * invR + c.x * invC;
        op[(size_t)(2 * j + 1) * 4096] = a.y * invA + r.y * invR + c.y * invC;
    }
}

// ---------------------------------------------------------------------------
extern "C" void kernel_launch(void* const* d_in, const int* in_sizes, int n_in,
                              void* d_out, int out_size)
{
    const float* fm   = (const float*)d_in[0];
    const float* wq   = (const float*)d_in[1];
    const float* wk   = (const float*)d_in[2];
    const float* wv   = (const float*)d_in[3];
    const float* relh = (const float*)d_in[4];
    const float* relw = (const float*)d_in[5];
    float* out = (float*)d_out;

    const int smem_bytes = 2 * EHE * EWE * CST * (int)sizeof(float);  // 220800
    cudaFuncSetAttribute(attn_kernel,
                         cudaFuncAttributeMaxDynamicSharedMemorySize, smem_bytes);

    conv_gemm_kernel<<<dim3(NPOS / 128, 2, 3), 128>>>(fm, wq, wk, wv);
    attn_kernel<<<dim3(WW / TILE_W, HH / TILE_H, BB * 8), 512, smem_bytes>>>(
        relh, relw, out);
}

// round 16
// speedup vs baseline: 1.4881x; 1.0883x over previous
#include <cuda_runtime.h>
#include <cuda_fp16.h>
#include <cstdint>

// ---------------------------------------------------------------------------
// Temporal attention, B=2, H=W=64, C=128, GROUPS=8 (cg=16), K=7, PAD=3, REFINE
// Stage 1: conv1x1 GEMM, 64o x 128p blocks, 128 thr, 8x8/thread, f32x2.
//          (verbatim from the 54.0us passing kernel)
// Stage 2: fused windowed attention, 16x32 tile / 512 threads, f32x2.
//          K fp32 (stride 20 floats). V fp16 (stride 24 halfs = 48B):
//          TWO LDS.128 deliver the 16 V channels (8 halves each).
// ---------------------------------------------------------------------------

#define HH   64
#define WW   64
#define BB   2
#define NCH  128
#define NPOS 8192            // BB*HH*WW

__device__ float g_Q[NCH * NPOS];
__device__ float g_K[NCH * NPOS];
__device__ float g_V[NCH * NPOS];

// ---- f32x2 packed helpers -------------------------------------------------
#define MUL_F32X2(out, a, b) \
    asm("mul.rn.f32x2 %0, %1, %2;" : "=l"(out) : "l"(a), "l"(b))
#define ADD_F32X2(out, a, b) \
    asm("add.rn.f32x2 %0, %1, %2;" : "=l"(out) : "l"(a), "l"(b))
#define FMA_F32X2(d, a, b, c) \
    asm("fma.rn.f32x2 %0, %1, %2, %3;" : "=l"(d) : "l"(a), "l"(b), "l"(c))

__device__ __forceinline__ uint64_t pack2(float lo, float hi) {
    uint64_t r;
    asm("mov.b64 %0, {%1, %2};" : "=l"(r)
        : "r"(__float_as_uint(lo)), "r"(__float_as_uint(hi)));
    return r;
}
__device__ __forceinline__ float2 unpack2(uint64_t u) {
    double d = __longlong_as_double((long long)u);
    return make_float2(__int_as_float(__double2loint(d)),
                       __int_as_float(__double2hiint(d)));
}
__device__ __forceinline__ uint64_t d2u(double d) {
    return (uint64_t)__double_as_longlong(d);
}

// ---------------------------------------------------------------------------
// Stage 1: C[o][p] = sum_c W[o][c] * X[c][p]   (verbatim known-good)
// ---------------------------------------------------------------------------
__global__ void __launch_bounds__(128, 3) conv_gemm_kernel(
    const float* __restrict__ fm,
    const float* __restrict__ wq,
    const float* __restrict__ wk,
    const float* __restrict__ wv)
{
    const int z = blockIdx.z;
    const float* Wm = (z == 0) ? wk : (z == 1) ? wv : wq;
    float* C        = (z == 0) ? g_K : (z == 1) ? g_V : g_Q;
    const int cbase = (z == 2) ? 128 : 0;

    const int p0  = blockIdx.x * 128;
    const int o0  = blockIdx.y * 64;
    const int b   = p0 >> 12;
    const int hw0 = p0 & 4095;
    const float* Xbase = fm + (size_t)b * (256 * 4096) + (size_t)cbase * 4096 + hw0;

    __shared__ float As[16][64];      // [k][o]
    __shared__ float Bs[16][128];     // [k][p]

    const int tid = threadIdx.x;
    const int tx  = tid & 15;
    const int ty  = tid >> 4;         // 0..7

    const int ao  = tid >> 1;         // o row 0..63
    const int akq = (tid & 1) * 8;    // k sub-offset 0 or 8
    const int bkr = tid >> 3;         // k row 0..15
    const int bpc = (tid & 7) * 16;   // p col, 16 floats per thread

    uint64_t acc[8][4];
#pragma unroll
    for (int r = 0; r < 8; r++)
#pragma unroll
        for (int c = 0; c < 4; c++) acc[r][c] = 0ull;

    float4 af0 = *(const float4*)(Wm + (o0 + ao) * 128 + akq);
    float4 af1 = *(const float4*)(Wm + (o0 + ao) * 128 + akq + 4);
    float4 bf0 = *(const float4*)(Xbase + (size_t)bkr * 4096 + bpc);
    float4 bf1 = *(const float4*)(Xbase + (size_t)bkr * 4096 + bpc + 4);
    float4 bf2 = *(const float4*)(Xbase + (size_t)bkr * 4096 + bpc + 8);
    float4 bf3 = *(const float4*)(Xbase + (size_t)bkr * 4096 + bpc + 12);

    for (int k0 = 0; k0 < 128; k0 += 16) {
        As[akq + 0][ao] = af0.x; As[akq + 1][ao] = af0.y;
        As[akq + 2][ao] = af0.z; As[akq + 3][ao] = af0.w;
        As[akq + 4][ao] = af1.x; As[akq + 5][ao] = af1.y;
        As[akq + 6][ao] = af1.z; As[akq + 7][ao] = af1.w;
        *(float4*)&Bs[bkr][bpc]      = bf0;
        *(float4*)&Bs[bkr][bpc + 4]  = bf1;
        *(float4*)&Bs[bkr][bpc + 8]  = bf2;
        *(float4*)&Bs[bkr][bpc + 12] = bf3;
        __syncthreads();

        if (k0 < 112) {
            af0 = *(const float4*)(Wm + (o0 + ao) * 128 + k0 + 16 + akq);
            af1 = *(const float4*)(Wm + (o0 + ao) * 128 + k0 + 16 + akq + 4);
            const float* Xn = Xbase + (size_t)(k0 + 16 + bkr) * 4096 + bpc;
            bf0 = *(const float4*)(Xn);
            bf1 = *(const float4*)(Xn + 4);
            bf2 = *(const float4*)(Xn + 8);
            bf3 = *(const float4*)(Xn + 12);
        }

#pragma unroll
        for (int kk = 0; kk < 16; kk++) {
            float4 a0 = *(const float4*)&As[kk][ty * 4];
            float4 a1 = *(const float4*)&As[kk][32 + ty * 4];
            float4 b0 = *(const float4*)&Bs[kk][tx * 4];
            float4 b1 = *(const float4*)&Bs[kk][64 + tx * 4];
            uint64_t bp0 = pack2(b0.x, b0.y), bp1 = pack2(b0.z, b0.w);
            uint64_t bp2 = pack2(b1.x, b1.y), bp3 = pack2(b1.z, b1.w);
            uint64_t ad;
            ad = pack2(a0.x, a0.x);
            FMA_F32X2(acc[0][0], ad, bp0, acc[0][0]);
            FMA_F32X2(acc[0][1], ad, bp1, acc[0][1]);
            FMA_F32X2(acc[0][2], ad, bp2, acc[0][2]);
            FMA_F32X2(acc[0][3], ad, bp3, acc[0][3]);
            ad = pack2(a0.y, a0.y);
            FMA_F32X2(acc[1][0], ad, bp0, acc[1][0]);
            FMA_F32X2(acc[1][1], ad, bp1, acc[1][1]);
            FMA_F32X2(acc[1][2], ad, bp2, acc[1][2]);
            FMA_F32X2(acc[1][3], ad, bp3, acc[1][3]);
            ad = pack2(a0.z, a0.z);
            FMA_F32X2(acc[2][0], ad, bp0, acc[2][0]);
            FMA_F32X2(acc[2][1], ad, bp1, acc[2][1]);
            FMA_F32X2(acc[2][2], ad, bp2, acc[2][2]);
            FMA_F32X2(acc[2][3], ad, bp3, acc[2][3]);
            ad = pack2(a0.w, a0.w);
            FMA_F32X2(acc[3][0], ad, bp0, acc[3][0]);
            FMA_F32X2(acc[3][1], ad, bp1, acc[3][1]);
            FMA_F32X2(acc[3][2], ad, bp2, acc[3][2]);
            FMA_F32X2(acc[3][3], ad, bp3, acc[3][3]);
            ad = pack2(a1.x, a1.x);
            FMA_F32X2(acc[4][0], ad, bp0, acc[4][0]);
            FMA_F32X2(acc[4][1], ad, bp1, acc[4][1]);
            FMA_F32X2(acc[4][2], ad, bp2, acc[4][2]);
            FMA_F32X2(acc[4][3], ad, bp3, acc[4][3]);
            ad = pack2(a1.y, a1.y);
            FMA_F32X2(acc[5][0], ad, bp0, acc[5][0]);
            FMA_F32X2(acc[5][1], ad, bp1, acc[5][1]);
            FMA_F32X2(acc[5][2], ad, bp2, acc[5][2]);
            FMA_F32X2(acc[5][3], ad, bp3, acc[5][3]);
            ad = pack2(a1.z, a1.z);
            FMA_F32X2(acc[6][0], ad, bp0, acc[6][0]);
            FMA_F32X2(acc[6][1], ad, bp1, acc[6][1]);
            FMA_F32X2(acc[6][2], ad, bp2, acc[6][2]);
            FMA_F32X2(acc[6][3], ad, bp3, acc[6][3]);
            ad = pack2(a1.w, a1.w);
            FMA_F32X2(acc[7][0], ad, bp0, acc[7][0]);
            FMA_F32X2(acc[7][1], ad, bp1, acc[7][1]);
            FMA_F32X2(acc[7][2], ad, bp2, acc[7][2]);
            FMA_F32X2(acc[7][3], ad, bp3, acc[7][3]);
        }
        __syncthreads();
    }

#pragma unroll
    for (int r = 0; r < 8; r++) {
        const int o = o0 + ((r < 4) ? (ty * 4 + r) : (32 + ty * 4 + (r - 4)));
        float2 u0 = unpack2(acc[r][0]);
        float2 u1 = unpack2(acc[r][1]);
        float2 u2 = unpack2(acc[r][2]);
        float2 u3 = unpack2(acc[r][3]);
        float* Cp = C + (size_t)o * NPOS + p0;
        *(float4*)(Cp + tx * 4)      = make_float4(u0.x, u0.y, u1.x, u1.y);
        *(float4*)(Cp + 64 + tx * 4) = make_float4(u2.x, u2.y, u3.x, u3.y);
    }
}

// ---------------------------------------------------------------------------
// Stage 2
// ---------------------------------------------------------------------------
#define TILE_H 16
#define TILE_W 32
#define EHE    (TILE_H + 14)   // 30
#define EWE    (TILE_W + 14)   // 46
#define CST    20              // K stride in floats (80B): conflict-free
#define VSTH   24              // V stride in halfs  (48B): conflict-free

__device__ __forceinline__ float dot16(const float* kp, const uint64_t* qp)
{
    const double2* kd = (const double2*)kp;
    double2 k01 = kd[0], k23 = kd[1], k45 = kd[2], k67 = kd[3];
    uint64_t d0, d1;
    MUL_F32X2(d0, qp[0], d2u(k01.x));
    MUL_F32X2(d1, qp[1], d2u(k01.y));
    FMA_F32X2(d0, qp[2], d2u(k23.x), d0);
    FMA_F32X2(d1, qp[3], d2u(k23.y), d1);
    FMA_F32X2(d0, qp[4], d2u(k45.x), d0);
    FMA_F32X2(d1, qp[5], d2u(k45.y), d1);
    FMA_F32X2(d0, qp[6], d2u(k67.x), d0);
    FMA_F32X2(d1, qp[7], d2u(k67.y), d1);
    ADD_F32X2(d0, d0, d1);
    float2 f = unpack2(d0);
    return f.x + f.y;
}

// TWO LDS.128 -> 16 fp16 V channels -> 8 packed f32 pairs.
// One uint32 = one half2 (2 channels). uint4 = 8 channels.
__device__ __forceinline__ void loadv16(const __half* vp, uint64_t* vv)
{
    uint4 raw0 = *(const uint4*)vp;        // channels 0..7
    uint4 raw1 = *(const uint4*)(vp + 8);  // channels 8..15
    float2 f;
    f = __half22float2(*(__half2*)&raw0.x); vv[0] = pack2(f.x, f.y);
    f = __half22float2(*(__half2*)&raw0.y); vv[1] = pack2(f.x, f.y);
    f = __half22float2(*(__half2*)&raw0.z); vv[2] = pack2(f.x, f.y);
    f = __half22float2(*(__half2*)&raw0.w); vv[3] = pack2(f.x, f.y);
    f = __half22float2(*(__half2*)&raw1.x); vv[4] = pack2(f.x, f.y);
    f = __half22float2(*(__half2*)&raw1.y); vv[5] = pack2(f.x, f.y);
    f = __half22float2(*(__half2*)&raw1.z); vv[6] = pack2(f.x, f.y);
    f = __half22float2(*(__half2*)&raw1.w); vv[7] = pack2(f.x, f.y);
}

__device__ __forceinline__ void accv(uint64_t* acc, const uint64_t* vv, uint64_t ep)
{
#pragma unroll
    for (int j = 0; j < 8; j++) FMA_F32X2(acc[j], ep, vv[j], acc[j]);
}

__global__ void __launch_bounds__(512, 1) attn_kernel(
    const float* __restrict__ relh,
    const float* __restrict__ relw,
    float* __restrict__ out)
{
    extern __shared__ float sm[];
    float*  Ks = sm;                                 // 1380*20 floats = 110400B
    __half* Vh = (__half*)(sm + EHE * EWE * CST);    // 1380*24 halfs  =  66240B

    const int bz = blockIdx.z;          // b*8 + g
    const int b  = bz >> 3;
    const int g  = bz & 7;
    const int y0 = blockIdx.y * TILE_H;
    const int x0 = blockIdx.x * TILE_W;
    const int ch0 = g * 16;
    const int tid = threadIdx.x;

    // ---- load extended K (fp32) + V (fp16) tiles, zero outside image ----
    const float* Kbase = g_K + (size_t)ch0 * NPOS + b * 4096;
    const float* Vbase = g_V + (size_t)ch0 * NPOS + b * 4096;
    for (int idx = tid; idx < 16 * EHE * EWE; idx += 512) {
        int row = idx / EWE;            // c*EHE + yy
        int xx  = idx - row * EWE;
        int c   = row / EHE;
        int yy  = row - c * EHE;
        int gy = y0 + yy - 7, gx = x0 + xx - 7;
        float kv = 0.f, vv = 0.f;
        if ((unsigned)gy < (unsigned)HH && (unsigned)gx < (unsigned)WW) {
            int off = c * NPOS + gy * WW + gx;
            kv = Kbase[off];
            vv = Vbase[off];
        }
        int p = yy * EWE + xx;
        Ks[p * CST + c]  = kv;
        Vh[p * VSTH + c] = __float2half_rn(vv);
    }
    __syncthreads();

    const int px = tid & 31, py = tid >> 5;
    const int h = y0 + py, w = x0 + px;

    // ---- per-thread query ----
    float q[16];
    const float* Qp = g_Q + (size_t)ch0 * NPOS + b * 4096 + h * WW + w;
#pragma unroll
    for (int c = 0; c < 16; c++) q[c] = Qp[(size_t)c * NPOS];

    // ---- rel bias, exponentiated: g<4 -> rel_h(dy), g>=4 -> rel_w(dx) ----
    const bool use_h = (g < 4);
    const float* rel = use_h ? (relh + ch0 * 7) : (relw + (ch0 - 64) * 7);
    float eb[7];
#pragma unroll
    for (int i = 0; i < 7; i++) {
        float s = 0.f;
#pragma unroll
        for (int c = 0; c < 16; c++) s += q[c] * __ldg(&rel[c * 7 + i]);
        eb[i] = __expf(s);
    }

    uint64_t qp[8];
#pragma unroll
    for (int j = 0; j < 8; j++) qp[j] = pack2(q[2 * j], q[2 * j + 1]);

    float sA = 0.f, sR = 0.f, sC = 0.f;
    uint64_t vA[8], vR[8], vC[8];
#pragma unroll
    for (int j = 0; j < 8; j++) { vA[j] = 0ull; vR[j] = 0ull; vC[j] = 0ull; }

    // ===== 2D 7x7 window; dy==3 feeds row branch, dx==3 col branch =========
#pragma unroll
    for (int dy = 0; dy < 7; dy++) {
#pragma unroll
        for (int dx = 0; dx < 7; dx++) {
            const int p = (py + 4 + dy) * EWE + (px + 4 + dx);
            float d  = dot16(&Ks[p * CST], qp);
            float ed = __expf(d);
            float eA = ed * eb[use_h ? dy : dx];
            uint64_t vv[8];
            loadv16(&Vh[p * VSTH], vv);
            sA += eA;
            accv(vA, vv, pack2(eA, eA));
            if (dy == 3) { sR += ed; accv(vR, vv, pack2(ed, ed)); }
            if (dx == 3) { sC += ed; accv(vC, vv, pack2(ed, ed)); }
        }
    }

    // ===== remaining row positions j in {0..3, 11..14} =====
#pragma unroll
    for (int t = 0; t < 8; t++) {
        const int j = (t < 4) ? t : (t + 7);
        const int p = (py + 7) * EWE + (px + j);
        float ed = __expf(dot16(&Ks[p * CST], qp));
        uint64_t vv[8];
        loadv16(&Vh[p * VSTH], vv);
        sR += ed;
        accv(vR, vv, pack2(ed, ed));
    }
    // ===== remaining col positions i in {0..3, 11..14} =====
#pragma unroll
    for (int t = 0; t < 8; t++) {
        const int i = (t < 4) ? t : (t + 7);
        const int p = (py + i) * EWE + (px + 7);
        float ed = __expf(dot16(&Ks[p * CST], qp));
        uint64_t vv[8];
        loadv16(&Vh[p * VSTH], vv);
        sC += ed;
        accv(vC, vv, pack2(ed, ed));
    }

    // ---- combine and write output (B, 128, 64, 64) ----
    const float invA = 1.f / sA, invR = 1.f / sR, invC = 1.f / sC;
    float* op = out + (size_t)(b * NCH + ch0) * 4096 + h * WW + w;
#pragma unroll
    for (int j = 0; j < 8; j++) {
        float2 a = unpack2(vA[j]);
        float2 r = unpack2(vR[j]);
        float2 c = unpack2(vC[j]);
        op[(size_t)(2 * j) * 4096]     = a.x * invA + r.x * invR + c.x * invC;
        op[(size_t)(2 * j + 1) * 4096] = a.y * invA + r.y * invR + c.y * invC;
    }
}

// ---------------------------------------------------------------------------
extern "C" void kernel_launch(void* const* d_in, const int* in_sizes, int n_in,
                              void* d_out, int out_size)
{
    const float* fm   = (const float*)d_in[0];
    const float* wq   = (const float*)d_in[1];
    const float* wk   = (const float*)d_in[2];
    const float* wv   = (const float*)d_in[3];
    const float* relh = (const float*)d_in[4];
    const float* relw = (const float*)d_in[5];
    float* out = (float*)d_out;

    const int smem_bytes = EHE * EWE * CST * 4 + EHE * EWE * VSTH * 2;  // 176640
    cudaFuncSetAttribute(attn_kernel,
                         cudaFuncAttributeMaxDynamicSharedMemorySize, smem_bytes);

    conv_gemm_kernel<<<dim3(NPOS / 128, 2, 3), 128>>>(fm, wq, wk, wv);
    attn_kernel<<<dim3(WW / TILE_W, HH / TILE_H, BB * 8), 512, smem_bytes>>>(
        relh, relw, out);
}